// round 7
// baseline (speedup 1.0000x reference)
#include <cuda_runtime.h>

// KAN 1-D conv, B=32 I=8 O=32 W=8192 K=5 Wo=8188, 9 channels (silu + 8 cubic B-splines).
// R7: fused weights moved to __constant__ (served by const port, off the L1 pipe).
// Prep kernel + cudaMemcpyToSymbolAsync + main kernel. Features in smem (38KB),
// 4o x 4w thread tile, o-pair fma.rn.f32x2, conflict-free feature LDS.128.

#define B_DIM 32
#define I_DIM 8
#define O_DIM 32
#define W_IN 8192
#define KSZ 5
#define W_OUT (W_IN - KSZ + 1)   // 8188
#define NC 9
#define TILE_W 128
#define FP (TILE_W + KSZ - 1)    // 132
#define NTHREADS 256
#define NTILES ((W_OUT + TILE_W - 1) / TILE_W)   // 64

__host__ __device__ constexpr float gridc(int j) {
    return (float)(j - 3) * 0.4f - 1.0f;
}

#define WC_ELEMS (I_DIM * KSZ * NC * O_DIM)   // 11520 floats = 45KB (< 64KB cbank)
#define FS_ELEMS (I_DIM * NC * FP)            // 9504 floats = 38016 B smem

__constant__ float cWc[WC_ELEMS];             // [i][k][c][o], o contiguous
__device__   float g_wc[WC_ELEMS];            // staging for the fused weights

__device__ __forceinline__ unsigned long long splat2(float f) {
    unsigned long long r;
    asm("mov.b64 %0, {%1, %1};" : "=l"(r) : "r"(__float_as_uint(f)));
    return r;
}
__device__ __forceinline__ void ffma2(unsigned long long& d,
                                      unsigned long long a,
                                      unsigned long long b) {
    asm("fma.rn.f32x2 %0, %1, %2, %0;" : "+l"(d) : "l"(a), "l"(b));
}
__device__ __forceinline__ float lo32(unsigned long long v) {
    return __uint_as_float((unsigned)(v & 0xffffffffull));
}
__device__ __forceinline__ float hi32(unsigned long long v) {
    return __uint_as_float((unsigned)(v >> 32));
}

// Weight-quad load from __constant__, guaranteed const-port path:
// generic address -> cvta.to.const -> ld.const.v2.u64 (one LDC.128).
__device__ __forceinline__ ulonglong2 ldc_quad(const float* gptr) {
    ulonglong2 v;
    asm("{\n\t"
        ".reg .u64 t;\n\t"
        "cvta.to.const.u64 t, %2;\n\t"
        "ld.const.v2.u64 {%0, %1}, [t];\n\t"
        "}"
        : "=l"(v.x), "=l"(v.y) : "l"(gptr));
    return v;
}

// ---- Prep: fuse base_weight / spline_weight*scaler into g_wc ----
__global__ void prep_weights(const float* __restrict__ base_weight,
                             const float* __restrict__ spline_weight,
                             const float* __restrict__ spline_scaler)
{
    int idx = blockIdx.x * blockDim.x + threadIdx.x;   // flat (o,i,k), 1280 items
    if (idx >= O_DIM * I_DIM * KSZ) return;
    int k = idx % KSZ;
    int r = idx / KSZ;
    int i = r % I_DIM;
    int o = r / I_DIM;
    float bw = base_weight[idx];
    float sc = spline_scaler[idx];
    float* dst = &g_wc[((i * KSZ + k) * NC) * O_DIM + o];
    dst[0] = bw;
    const float* sw = &spline_weight[idx * 8];
    #pragma unroll
    for (int c = 0; c < 8; c++)
        dst[(c + 1) * O_DIM] = sw[c] * sc;
}

__global__ __launch_bounds__(NTHREADS)
void kan_conv1d_kernel(const float* __restrict__ x,
                       float* __restrict__ out)
{
    extern __shared__ float smem[];
    float* Fs = smem;                 // [I][NC][FP]

    const int tid = threadIdx.x;
    const int b   = blockIdx.y;
    const int w0  = blockIdx.x * TILE_W;

    // ---- Phase 2: per-element features (silu + 8 cubic B-spline bases) ----
    for (int e = tid; e < I_DIM * FP; e += NTHREADS) {
        int i = e / FP;
        int p = e % FP;
        int gw = w0 + p;
        float xv = (gw < W_IN) ? x[(b * I_DIM + i) * W_IN + gw] : 0.0f;

        float* f = &Fs[i * NC * FP + p];
        f[0] = xv / (1.0f + __expf(-xv));

        float b0[11];
        #pragma unroll
        for (int j = 0; j < 11; j++)
            b0[j] = (xv >= gridc(j) && xv < gridc(j + 1)) ? 1.0f : 0.0f;
        float b1[10];
        #pragma unroll
        for (int j = 0; j < 10; j++) {
            float l = (xv - gridc(j))     * (1.0f / (gridc(j + 1) - gridc(j)));
            float r = (gridc(j + 2) - xv) * (1.0f / (gridc(j + 2) - gridc(j + 1)));
            b1[j] = l * b0[j] + r * b0[j + 1];
        }
        float b2[9];
        #pragma unroll
        for (int j = 0; j < 9; j++) {
            float l = (xv - gridc(j))     * (1.0f / (gridc(j + 2) - gridc(j)));
            float r = (gridc(j + 3) - xv) * (1.0f / (gridc(j + 3) - gridc(j + 1)));
            b2[j] = l * b1[j] + r * b1[j + 1];
        }
        #pragma unroll
        for (int j = 0; j < 8; j++) {
            float l = (xv - gridc(j))     * (1.0f / (gridc(j + 3) - gridc(j)));
            float r = (gridc(j + 4) - xv) * (1.0f / (gridc(j + 4) - gridc(j + 1)));
            f[(j + 1) * FP] = l * b2[j] + r * b2[j + 1];
        }
    }
    __syncthreads();

    // ---- Phase 3: MAC. Thread owns o in [o0,o0+4), w in [wt*4, wt*4+4). ----
    const int wt = tid & 31;      // 32 w-lanes * 4 w = 128 w
    const int og = tid >> 5;      // 8 o-groups * 4 o = 32 o   (warp-uniform)
    const int o0 = og * 4;

    unsigned long long acc[2][4];
    #pragma unroll
    for (int p = 0; p < 2; p++)
        #pragma unroll
        for (int u = 0; u < 4; u++)
            acc[p][u] = 0ull;

    #pragma unroll 1
    for (int i = 0; i < I_DIM; i++) {
        #pragma unroll 3
        for (int c = 0; c < NC; c++) {
            // 8 consecutive feature positions [wt*4, wt*4+8): two LDS.128,
            // lane stride 16B -> conflict-free.
            const float4* f4 = (const float4*)(Fs + (i * NC + c) * FP + wt * 4);
            float4 a0 = f4[0];
            float4 a1 = f4[1];
            unsigned long long fs[8];
            fs[0] = splat2(a0.x); fs[1] = splat2(a0.y);
            fs[2] = splat2(a0.z); fs[3] = splat2(a0.w);
            fs[4] = splat2(a1.x); fs[5] = splat2(a1.y);
            fs[6] = splat2(a1.z); fs[7] = splat2(a1.w);

            #pragma unroll
            for (int k = 0; k < KSZ; k++) {
                // weight quad {o0..o0+3} from __constant__ via the const port
                ulonglong2 wq = ldc_quad(&cWc[((i * KSZ + k) * NC + c) * O_DIM + o0]);
                #pragma unroll
                for (int u = 0; u < 4; u++) {
                    ffma2(acc[0][u], wq.x, fs[u + k]);
                    ffma2(acc[1][u], wq.y, fs[u + k]);
                }
            }
        }
    }

    // ---- Phase 4: store. 4 o-rows x 4 consecutive w per thread. ----
    const int wbase = w0 + wt * 4;
    const bool full = (wbase + 4 <= W_OUT);
    #pragma unroll
    for (int p = 0; p < 2; p++) {
        float lv[4], hv[4];
        #pragma unroll
        for (int u = 0; u < 4; u++) {
            lv[u] = lo32(acc[p][u]);
            hv[u] = hi32(acc[p][u]);
        }
        int olo = o0 + 2 * p;
        float* rlo = out + ((size_t)(b * O_DIM + olo)) * W_OUT + wbase;
        float* rhi = rlo + W_OUT;
        if (full) {
            *(float4*)rlo = make_float4(lv[0], lv[1], lv[2], lv[3]);
            *(float4*)rhi = make_float4(hv[0], hv[1], hv[2], hv[3]);
        } else {
            #pragma unroll
            for (int u = 0; u < 4; u++) {
                if (wbase + u < W_OUT) {
                    rlo[u] = lv[u];
                    rhi[u] = hv[u];
                }
            }
        }
    }
}

extern "C" void kernel_launch(void* const* d_in, const int* in_sizes, int n_in,
                              void* d_out, int out_size)
{
    const float* x             = (const float*)d_in[0];
    const float* base_weight   = (const float*)d_in[1];
    const float* spline_weight = (const float*)d_in[2];
    const float* spline_scaler = (const float*)d_in[3];
    float* out = (float*)d_out;

    // 1) fuse weights into staging buffer
    prep_weights<<<5, 256>>>(base_weight, spline_weight, spline_scaler);

    // 2) staging -> constant bank (D2D async; graph-capturable memcpy node)
    void* wc_dev = nullptr;
    cudaGetSymbolAddress(&wc_dev, g_wc);
    cudaMemcpyToSymbolAsync(cWc, wc_dev, WC_ELEMS * sizeof(float), 0,
                            cudaMemcpyDeviceToDevice, 0);

    // 3) main kernel
    size_t smem_bytes = FS_ELEMS * sizeof(float);   // 38016
    cudaFuncSetAttribute(kan_conv1d_kernel,
                         cudaFuncAttributeMaxDynamicSharedMemorySize,
                         (int)smem_bytes);
    dim3 grid(NTILES, B_DIM);   // 64 x 32
    kan_conv1d_kernel<<<grid, NTHREADS, smem_bytes>>>(x, out);
}

// round 8
// speedup vs baseline: 1.9246x; 1.9246x over previous
#include <cuda_runtime.h>

// KAN 1-D conv, B=32 I=8 O=32 W=8192 K=5 Wo=8188, 9 channels (silu + 8 cubic B-splines).
// R8: TILE_W=256, 256 thr. 32 w-lanes x 8 warp-uniform o-groups; 8 w/thread in two
// stride-128 groups (conflict-free LDS.128 features). Weights in __constant__ via
// PLAIN indexing (native broadcast LDC.128; no inline asm). fma is the binding pipe.

#define B_DIM 32
#define I_DIM 8
#define O_DIM 32
#define W_IN 8192
#define KSZ 5
#define W_OUT (W_IN - KSZ + 1)   // 8188
#define NC 9
#define TILE_W 256
#define HALF_W 128
#define FP (TILE_W + KSZ - 1)    // 260
#define NTHREADS 256
#define NTILES ((W_OUT + TILE_W - 1) / TILE_W)   // 32

__host__ __device__ constexpr float gridc(int j) {
    return (float)(j - 3) * 0.4f - 1.0f;
}

#define WC_ELEMS (I_DIM * KSZ * NC * O_DIM)   // 11520 floats = 45KB (< 64KB cbank)
#define FS_ELEMS (I_DIM * NC * FP)            // 18720 floats = 74880 B smem

__constant__ float cWc[WC_ELEMS];             // [i][k][c][o], o contiguous
__device__   float g_wc[WC_ELEMS];            // staging buffer

__device__ __forceinline__ unsigned long long splat2(float f) {
    unsigned long long r;
    asm("mov.b64 %0, {%1, %1};" : "=l"(r) : "r"(__float_as_uint(f)));
    return r;
}
__device__ __forceinline__ void ffma2(unsigned long long& d,
                                      unsigned long long a,
                                      unsigned long long b) {
    asm("fma.rn.f32x2 %0, %1, %2, %0;" : "+l"(d) : "l"(a), "l"(b));
}
__device__ __forceinline__ float lo32(unsigned long long v) {
    return __uint_as_float((unsigned)(v & 0xffffffffull));
}
__device__ __forceinline__ float hi32(unsigned long long v) {
    return __uint_as_float((unsigned)(v >> 32));
}

// ---- Prep: fuse base_weight / spline_weight*scaler into g_wc ----
__global__ void prep_weights(const float* __restrict__ base_weight,
                             const float* __restrict__ spline_weight,
                             const float* __restrict__ spline_scaler)
{
    int idx = blockIdx.x * blockDim.x + threadIdx.x;   // flat (o,i,k), 1280 items
    if (idx >= O_DIM * I_DIM * KSZ) return;
    int k = idx % KSZ;
    int r = idx / KSZ;
    int i = r % I_DIM;
    int o = r / I_DIM;
    float bw = base_weight[idx];
    float sc = spline_scaler[idx];
    float* dst = &g_wc[((i * KSZ + k) * NC) * O_DIM + o];
    dst[0] = bw;
    const float* sw = &spline_weight[idx * 8];
    #pragma unroll
    for (int c = 0; c < 8; c++)
        dst[(c + 1) * O_DIM] = sw[c] * sc;
}

__global__ __launch_bounds__(NTHREADS, 2)
void kan_conv1d_kernel(const float* __restrict__ x,
                       float* __restrict__ out)
{
    extern __shared__ float smem[];
    float* Fs = smem;                 // [I][NC][FP]

    const int tid = threadIdx.x;
    const int b   = blockIdx.y;
    const int w0  = blockIdx.x * TILE_W;

    // ---- Phase 2: per-element features (silu + 8 cubic B-spline bases) ----
    for (int e = tid; e < I_DIM * FP; e += NTHREADS) {
        int i = e / FP;
        int p = e % FP;
        int gw = w0 + p;
        float xv = (gw < W_IN) ? x[(b * I_DIM + i) * W_IN + gw] : 0.0f;

        float* f = &Fs[i * NC * FP + p];
        f[0] = xv / (1.0f + __expf(-xv));

        float b0[11];
        #pragma unroll
        for (int j = 0; j < 11; j++)
            b0[j] = (xv >= gridc(j) && xv < gridc(j + 1)) ? 1.0f : 0.0f;
        float b1[10];
        #pragma unroll
        for (int j = 0; j < 10; j++) {
            float l = (xv - gridc(j))     * (1.0f / (gridc(j + 1) - gridc(j)));
            float r = (gridc(j + 2) - xv) * (1.0f / (gridc(j + 2) - gridc(j + 1)));
            b1[j] = l * b0[j] + r * b0[j + 1];
        }
        float b2[9];
        #pragma unroll
        for (int j = 0; j < 9; j++) {
            float l = (xv - gridc(j))     * (1.0f / (gridc(j + 2) - gridc(j)));
            float r = (gridc(j + 3) - xv) * (1.0f / (gridc(j + 3) - gridc(j + 1)));
            b2[j] = l * b1[j] + r * b1[j + 1];
        }
        #pragma unroll
        for (int j = 0; j < 8; j++) {
            float l = (xv - gridc(j))     * (1.0f / (gridc(j + 3) - gridc(j)));
            float r = (gridc(j + 4) - xv) * (1.0f / (gridc(j + 4) - gridc(j + 1)));
            f[(j + 1) * FP] = l * b2[j] + r * b2[j + 1];
        }
    }
    __syncthreads();

    // ---- Phase 3: MAC. Thread: o in [o0,o0+4), w = wt*4+u + 128g (u<4, g<2). ----
    const int wt = tid & 31;      // 32 w-lanes (full warp -> warp-uniform og)
    const int og = tid >> 5;      // 8 o-groups, one per warp
    const int o0 = og * 4;

    // acc[g][p][u]: group g, o-pair p = (o0+2p, o0+2p+1) in f32x2 lanes, w = wt*4+u+128g
    unsigned long long acc[2][2][4];
    #pragma unroll
    for (int g = 0; g < 2; g++)
        #pragma unroll
        for (int p = 0; p < 2; p++)
            #pragma unroll
            for (int u = 0; u < 4; u++)
                acc[g][p][u] = 0ull;

    #pragma unroll 1
    for (int i = 0; i < I_DIM; i++) {
        #pragma unroll 3
        for (int c = 0; c < NC; c++) {
            const float* frow = Fs + (i * NC + c) * FP + wt * 4;
            // group A: [wt*4, wt*4+8)  — lanes stride 16B over 512B: conflict-free
            float4 a0 = *(const float4*)(frow);
            float4 a1 = *(const float4*)(frow + 4);
            // group B: [wt*4+128, wt*4+136)
            float4 c0 = *(const float4*)(frow + HALF_W);
            float4 c1 = *(const float4*)(frow + HALF_W + 4);

            unsigned long long fsA[8], fsB[8];
            fsA[0] = splat2(a0.x); fsA[1] = splat2(a0.y);
            fsA[2] = splat2(a0.z); fsA[3] = splat2(a0.w);
            fsA[4] = splat2(a1.x); fsA[5] = splat2(a1.y);
            fsA[6] = splat2(a1.z); fsA[7] = splat2(a1.w);
            fsB[0] = splat2(c0.x); fsB[1] = splat2(c0.y);
            fsB[2] = splat2(c0.z); fsB[3] = splat2(c0.w);
            fsB[4] = splat2(c1.x); fsB[5] = splat2(c1.y);
            fsB[6] = splat2(c1.z); fsB[7] = splat2(c1.w);

            #pragma unroll
            for (int k = 0; k < KSZ; k++) {
                // warp-uniform broadcast LDC.128 from constant bank (plain indexing)
                ulonglong2 wq = *(const ulonglong2*)
                    &cWc[((i * KSZ + k) * NC + c) * O_DIM + o0];
                #pragma unroll
                for (int u = 0; u < 4; u++) {
                    ffma2(acc[0][0][u], wq.x, fsA[u + k]);
                    ffma2(acc[0][1][u], wq.y, fsA[u + k]);
                    ffma2(acc[1][0][u], wq.x, fsB[u + k]);
                    ffma2(acc[1][1][u], wq.y, fsB[u + k]);
                }
            }
        }
    }

    // ---- Phase 4: store. 4 o-rows x (2 groups x 4 w) per thread. ----
    #pragma unroll
    for (int g = 0; g < 2; g++) {
        const int wbase = w0 + wt * 4 + g * HALF_W;
        const bool full = (wbase + 4 <= W_OUT);
        #pragma unroll
        for (int p = 0; p < 2; p++) {
            float lv[4], hv[4];
            #pragma unroll
            for (int u = 0; u < 4; u++) {
                lv[u] = lo32(acc[g][p][u]);
                hv[u] = hi32(acc[g][p][u]);
            }
            int olo = o0 + 2 * p;
            float* rlo = out + ((size_t)(b * O_DIM + olo)) * W_OUT + wbase;
            float* rhi = rlo + W_OUT;
            if (full) {
                *(float4*)rlo = make_float4(lv[0], lv[1], lv[2], lv[3]);
                *(float4*)rhi = make_float4(hv[0], hv[1], hv[2], hv[3]);
            } else {
                #pragma unroll
                for (int u = 0; u < 4; u++) {
                    if (wbase + u < W_OUT) {
                        rlo[u] = lv[u];
                        rhi[u] = hv[u];
                    }
                }
            }
        }
    }
}

extern "C" void kernel_launch(void* const* d_in, const int* in_sizes, int n_in,
                              void* d_out, int out_size)
{
    const float* x             = (const float*)d_in[0];
    const float* base_weight   = (const float*)d_in[1];
    const float* spline_weight = (const float*)d_in[2];
    const float* spline_scaler = (const float*)d_in[3];
    float* out = (float*)d_out;

    // 1) fuse weights into staging buffer
    prep_weights<<<5, 256>>>(base_weight, spline_weight, spline_scaler);

    // 2) staging -> constant bank (D2D async; graph-capturable memcpy node)
    void* wc_dev = nullptr;
    cudaGetSymbolAddress(&wc_dev, g_wc);
    cudaMemcpyToSymbolAsync(cWc, wc_dev, WC_ELEMS * sizeof(float), 0,
                            cudaMemcpyDeviceToDevice, 0);

    // 3) main kernel
    size_t smem_bytes = FS_ELEMS * sizeof(float);   // 74880
    cudaFuncSetAttribute(kan_conv1d_kernel,
                         cudaFuncAttributeMaxDynamicSharedMemorySize,
                         (int)smem_bytes);
    dim3 grid(NTILES, B_DIM);   // 32 x 32
    kan_conv1d_kernel<<<grid, NTHREADS, smem_bytes>>>(x, out);
}

// round 9
// speedup vs baseline: 3.2203x; 1.6732x over previous
#include <cuda_runtime.h>

// KAN 1-D conv, B=32 I=8 O=32 W=8192 K=5 Wo=8188, 9 channels (silu + 8 cubic B-splines).
// R9: 8o x 8w thread tile (fma-bound by construction). 128 thr = 4 warps, one warp
// per 8-o group; TILE_W=256 (two stride-128 w groups). Weights in smem (broadcast
// LDS.128). Feature buffer halved over i (two compute->MAC phases, acc in regs).

#define B_DIM 32
#define I_DIM 8
#define O_DIM 32
#define W_IN 8192
#define KSZ 5
#define W_OUT (W_IN - KSZ + 1)   // 8188
#define NC 9
#define TILE_W 256
#define HALF_W 128
#define FP (TILE_W + KSZ - 1)    // 260
#define NTHREADS 128
#define NTILES ((W_OUT + TILE_W - 1) / TILE_W)   // 32
#define I_HALF 4

__host__ __device__ constexpr float gridc(int j) {
    return (float)(j - 3) * 0.4f - 1.0f;
}

#define WC_ELEMS (I_DIM * KSZ * NC * O_DIM)    // 11520 floats = 46080 B
#define FS_ELEMS (I_HALF * NC * FP)            // 9360 floats  = 37440 B
#define SMEM_FLOATS (WC_ELEMS + FS_ELEMS)      // 20880 -> 83520 B (2 blocks/SM)

__device__ __forceinline__ unsigned long long splat2(float f) {
    unsigned long long r;
    asm("mov.b64 %0, {%1, %1};" : "=l"(r) : "r"(__float_as_uint(f)));
    return r;
}
__device__ __forceinline__ void ffma2(unsigned long long& d,
                                      unsigned long long a,
                                      unsigned long long b) {
    asm("fma.rn.f32x2 %0, %1, %2, %0;" : "+l"(d) : "l"(a), "l"(b));
}
__device__ __forceinline__ float lo32(unsigned long long v) {
    return __uint_as_float((unsigned)(v & 0xffffffffull));
}
__device__ __forceinline__ float hi32(unsigned long long v) {
    return __uint_as_float((unsigned)(v >> 32));
}

__global__ __launch_bounds__(NTHREADS, 2)
void kan_conv1d_kernel(const float* __restrict__ x,
                       const float* __restrict__ base_weight,
                       const float* __restrict__ spline_weight,
                       const float* __restrict__ spline_scaler,
                       float* __restrict__ out)
{
    extern __shared__ float smem[];
    float* Wc = smem;                 // [I][K][NC][O]  o contiguous
    float* Fs = smem + WC_ELEMS;      // [I_HALF][NC][FP]

    const int tid = threadIdx.x;
    const int b   = blockIdx.y;
    const int w0  = blockIdx.x * TILE_W;

    // ---- Phase 1: fuse weights into smem (idx enumerates (o,i,k) row-major) ----
    for (int idx = tid; idx < O_DIM * I_DIM * KSZ; idx += NTHREADS) {
        int k = idx % KSZ;
        int r = idx / KSZ;
        int i = r % I_DIM;
        int o = r / I_DIM;
        float bw = base_weight[idx];
        float sc = spline_scaler[idx];
        float* dst = &Wc[((i * KSZ + k) * NC) * O_DIM + o];
        dst[0] = bw;
        const float* sw = &spline_weight[idx * 8];
        #pragma unroll
        for (int c = 0; c < 8; c++)
            dst[(c + 1) * O_DIM] = sw[c] * sc;
    }

    // ---- MAC state: thread owns o in [o0,o0+8), w = wt*4+u + 128g ----
    const int wt = tid & 31;      // 32 w-lanes (warp-uniform og)
    const int og = tid >> 5;      // 4 o-groups of 8 o, one per warp
    const int o0 = og * 8;

    // acc[g][p][u]: w-group g, o-pair p = (o0+2p, o0+2p+1), w = wt*4+u+128g
    unsigned long long acc[2][4][4];
    #pragma unroll
    for (int g = 0; g < 2; g++)
        #pragma unroll
        for (int p = 0; p < 4; p++)
            #pragma unroll
            for (int u = 0; u < 4; u++)
                acc[g][p][u] = 0ull;

    #pragma unroll 1
    for (int h = 0; h < 2; h++) {
        if (h) __syncthreads();   // prior MAC must finish before Fs is overwritten

        // ---- Phase 2: features for i in [h*4, h*4+4) ----
        for (int e = tid; e < I_HALF * FP; e += NTHREADS) {
            int iL = e / FP;
            int p  = e % FP;
            int gw = w0 + p;
            int i  = h * I_HALF + iL;
            float xv = (gw < W_IN) ? x[(b * I_DIM + i) * W_IN + gw] : 0.0f;

            float* f = &Fs[iL * NC * FP + p];
            f[0] = xv / (1.0f + __expf(-xv));

            float b0[11];
            #pragma unroll
            for (int j = 0; j < 11; j++)
                b0[j] = (xv >= gridc(j) && xv < gridc(j + 1)) ? 1.0f : 0.0f;
            float b1[10];
            #pragma unroll
            for (int j = 0; j < 10; j++) {
                float l = (xv - gridc(j))     * (1.0f / (gridc(j + 1) - gridc(j)));
                float r = (gridc(j + 2) - xv) * (1.0f / (gridc(j + 2) - gridc(j + 1)));
                b1[j] = l * b0[j] + r * b0[j + 1];
            }
            float b2[9];
            #pragma unroll
            for (int j = 0; j < 9; j++) {
                float l = (xv - gridc(j))     * (1.0f / (gridc(j + 2) - gridc(j)));
                float r = (gridc(j + 3) - xv) * (1.0f / (gridc(j + 3) - gridc(j + 1)));
                b2[j] = l * b1[j] + r * b1[j + 1];
            }
            #pragma unroll
            for (int j = 0; j < 8; j++) {
                float l = (xv - gridc(j))     * (1.0f / (gridc(j + 3) - gridc(j)));
                float r = (gridc(j + 4) - xv) * (1.0f / (gridc(j + 4) - gridc(j + 1)));
                f[(j + 1) * FP] = l * b2[j] + r * b2[j + 1];
            }
        }
        __syncthreads();

        // ---- Phase 3: MAC over this i-half ----
        #pragma unroll 1
        for (int iL = 0; iL < I_HALF; iL++) {
            const int i = h * I_HALF + iL;
            #pragma unroll 3
            for (int c = 0; c < NC; c++) {
                const float* frow = Fs + (iL * NC + c) * FP + wt * 4;
                // group A: [wt*4, wt*4+8)      — lane stride 16B, conflict-free
                float4 a0 = *(const float4*)(frow);
                float4 a1 = *(const float4*)(frow + 4);
                // group B: [wt*4+128, wt*4+136)
                float4 c0 = *(const float4*)(frow + HALF_W);
                float4 c1 = *(const float4*)(frow + HALF_W + 4);

                unsigned long long fsA[8], fsB[8];
                fsA[0] = splat2(a0.x); fsA[1] = splat2(a0.y);
                fsA[2] = splat2(a0.z); fsA[3] = splat2(a0.w);
                fsA[4] = splat2(a1.x); fsA[5] = splat2(a1.y);
                fsA[6] = splat2(a1.z); fsA[7] = splat2(a1.w);
                fsB[0] = splat2(c0.x); fsB[1] = splat2(c0.y);
                fsB[2] = splat2(c0.z); fsB[3] = splat2(c0.w);
                fsB[4] = splat2(c1.x); fsB[5] = splat2(c1.y);
                fsB[6] = splat2(c1.z); fsB[7] = splat2(c1.w);

                #pragma unroll
                for (int k = 0; k < KSZ; k++) {
                    // two broadcast LDS.128: weight octet {o0..o0+7} = 4 f32x2 pairs
                    const float* wrow = &Wc[((i * KSZ + k) * NC + c) * O_DIM + o0];
                    ulonglong2 wq0 = *(const ulonglong2*)(wrow);
                    ulonglong2 wq1 = *(const ulonglong2*)(wrow + 4);
                    #pragma unroll
                    for (int u = 0; u < 4; u++) {
                        ffma2(acc[0][0][u], wq0.x, fsA[u + k]);
                        ffma2(acc[0][1][u], wq0.y, fsA[u + k]);
                        ffma2(acc[0][2][u], wq1.x, fsA[u + k]);
                        ffma2(acc[0][3][u], wq1.y, fsA[u + k]);
                        ffma2(acc[1][0][u], wq0.x, fsB[u + k]);
                        ffma2(acc[1][1][u], wq0.y, fsB[u + k]);
                        ffma2(acc[1][2][u], wq1.x, fsB[u + k]);
                        ffma2(acc[1][3][u], wq1.y, fsB[u + k]);
                    }
                }
            }
        }
    }

    // ---- Phase 4: store. 8 o-rows x (2 groups x 4 w) per thread. ----
    #pragma unroll
    for (int g = 0; g < 2; g++) {
        const int wbase = w0 + wt * 4 + g * HALF_W;
        const bool full = (wbase + 4 <= W_OUT);
        #pragma unroll
        for (int p = 0; p < 4; p++) {
            float lv[4], hv[4];
            #pragma unroll
            for (int u = 0; u < 4; u++) {
                lv[u] = lo32(acc[g][p][u]);
                hv[u] = hi32(acc[g][p][u]);
            }
            int olo = o0 + 2 * p;
            float* rlo = out + ((size_t)(b * O_DIM + olo)) * W_OUT + wbase;
            float* rhi = rlo + W_OUT;
            if (full) {
                *(float4*)rlo = make_float4(lv[0], lv[1], lv[2], lv[3]);
                *(float4*)rhi = make_float4(hv[0], hv[1], hv[2], hv[3]);
            } else {
                #pragma unroll
                for (int u = 0; u < 4; u++) {
                    if (wbase + u < W_OUT) {
                        rlo[u] = lv[u];
                        rhi[u] = hv[u];
                    }
                }
            }
        }
    }
}

extern "C" void kernel_launch(void* const* d_in, const int* in_sizes, int n_in,
                              void* d_out, int out_size)
{
    const float* x             = (const float*)d_in[0];
    const float* base_weight   = (const float*)d_in[1];
    const float* spline_weight = (const float*)d_in[2];
    const float* spline_scaler = (const float*)d_in[3];
    float* out = (float*)d_out;

    size_t smem_bytes = SMEM_FLOATS * sizeof(float);   // 83520
    cudaFuncSetAttribute(kan_conv1d_kernel,
                         cudaFuncAttributeMaxDynamicSharedMemorySize,
                         (int)smem_bytes);

    dim3 grid(NTILES, B_DIM);   // 32 x 32
    kan_conv1d_kernel<<<grid, NTHREADS, smem_bytes>>>(
        x, base_weight, spline_weight, spline_scaler, out);
}

// round 10
// speedup vs baseline: 3.3630x; 1.0443x over previous
#include <cuda_runtime.h>

// KAN 1-D conv, B=32 I=8 O=32 W=8192 K=5 Wo=8188, 9 channels (silu + 8 cubic B-splines).
// R10: R9's 8o x 8w tile + feature buffer shrunk to 2 i per phase -> 64.8 KB smem
// -> 3 blocks/SM (12 warps) for issue-rate headroom. 4 compute->MAC phases.

#define B_DIM 32
#define I_DIM 8
#define O_DIM 32
#define W_IN 8192
#define KSZ 5
#define W_OUT (W_IN - KSZ + 1)   // 8188
#define NC 9
#define TILE_W 256
#define HALF_W 128
#define FP (TILE_W + KSZ - 1)    // 260
#define NTHREADS 128
#define NTILES ((W_OUT + TILE_W - 1) / TILE_W)   // 32
#define I_CHUNK 2
#define N_PHASE (I_DIM / I_CHUNK)   // 4

__host__ __device__ constexpr float gridc(int j) {
    return (float)(j - 3) * 0.4f - 1.0f;
}

#define WC_ELEMS (I_DIM * KSZ * NC * O_DIM)    // 11520 floats = 46080 B
#define FS_ELEMS (I_CHUNK * NC * FP)           // 4680 floats  = 18720 B
#define SMEM_FLOATS (WC_ELEMS + FS_ELEMS)      // 16200 -> 64800 B (3 blocks/SM)

__device__ __forceinline__ unsigned long long splat2(float f) {
    unsigned long long r;
    asm("mov.b64 %0, {%1, %1};" : "=l"(r) : "r"(__float_as_uint(f)));
    return r;
}
__device__ __forceinline__ void ffma2(unsigned long long& d,
                                      unsigned long long a,
                                      unsigned long long b) {
    asm("fma.rn.f32x2 %0, %1, %2, %0;" : "+l"(d) : "l"(a), "l"(b));
}
__device__ __forceinline__ float lo32(unsigned long long v) {
    return __uint_as_float((unsigned)(v & 0xffffffffull));
}
__device__ __forceinline__ float hi32(unsigned long long v) {
    return __uint_as_float((unsigned)(v >> 32));
}

__global__ __launch_bounds__(NTHREADS, 3)
void kan_conv1d_kernel(const float* __restrict__ x,
                       const float* __restrict__ base_weight,
                       const float* __restrict__ spline_weight,
                       const float* __restrict__ spline_scaler,
                       float* __restrict__ out)
{
    extern __shared__ float smem[];
    float* Wc = smem;                 // [I][K][NC][O]  o contiguous
    float* Fs = smem + WC_ELEMS;      // [I_CHUNK][NC][FP]

    const int tid = threadIdx.x;
    const int b   = blockIdx.y;
    const int w0  = blockIdx.x * TILE_W;

    // ---- Phase 1: fuse weights into smem (idx enumerates (o,i,k) row-major) ----
    for (int idx = tid; idx < O_DIM * I_DIM * KSZ; idx += NTHREADS) {
        int k = idx % KSZ;
        int r = idx / KSZ;
        int i = r % I_DIM;
        int o = r / I_DIM;
        float bw = base_weight[idx];
        float sc = spline_scaler[idx];
        float* dst = &Wc[((i * KSZ + k) * NC) * O_DIM + o];
        dst[0] = bw;
        const float* sw = &spline_weight[idx * 8];
        #pragma unroll
        for (int c = 0; c < 8; c++)
            dst[(c + 1) * O_DIM] = sw[c] * sc;
    }

    // ---- MAC state: thread owns o in [o0,o0+8), w = wt*4+u + 128g ----
    const int wt = tid & 31;      // 32 w-lanes (warp-uniform og)
    const int og = tid >> 5;      // 4 o-groups of 8 o, one per warp
    const int o0 = og * 8;

    // acc[g][p][u]: w-group g, o-pair p = (o0+2p, o0+2p+1), w = wt*4+u+128g
    unsigned long long acc[2][4][4];
    #pragma unroll
    for (int g = 0; g < 2; g++)
        #pragma unroll
        for (int p = 0; p < 4; p++)
            #pragma unroll
            for (int u = 0; u < 4; u++)
                acc[g][p][u] = 0ull;

    #pragma unroll 1
    for (int h = 0; h < N_PHASE; h++) {
        if (h) __syncthreads();   // prior MAC must finish before Fs is overwritten

        // ---- Phase 2: features for i in [h*I_CHUNK, (h+1)*I_CHUNK) ----
        for (int e = tid; e < I_CHUNK * FP; e += NTHREADS) {
            int iL = e / FP;
            int p  = e % FP;
            int gw = w0 + p;
            int i  = h * I_CHUNK + iL;
            float xv = (gw < W_IN) ? x[(b * I_DIM + i) * W_IN + gw] : 0.0f;

            float* f = &Fs[iL * NC * FP + p];
            f[0] = xv / (1.0f + __expf(-xv));

            float b0[11];
            #pragma unroll
            for (int j = 0; j < 11; j++)
                b0[j] = (xv >= gridc(j) && xv < gridc(j + 1)) ? 1.0f : 0.0f;
            float b1[10];
            #pragma unroll
            for (int j = 0; j < 10; j++) {
                float l = (xv - gridc(j))     * (1.0f / (gridc(j + 1) - gridc(j)));
                float r = (gridc(j + 2) - xv) * (1.0f / (gridc(j + 2) - gridc(j + 1)));
                b1[j] = l * b0[j] + r * b0[j + 1];
            }
            float b2[9];
            #pragma unroll
            for (int j = 0; j < 9; j++) {
                float l = (xv - gridc(j))     * (1.0f / (gridc(j + 2) - gridc(j)));
                float r = (gridc(j + 3) - xv) * (1.0f / (gridc(j + 3) - gridc(j + 1)));
                b2[j] = l * b1[j] + r * b1[j + 1];
            }
            #pragma unroll
            for (int j = 0; j < 8; j++) {
                float l = (xv - gridc(j))     * (1.0f / (gridc(j + 3) - gridc(j)));
                float r = (gridc(j + 4) - xv) * (1.0f / (gridc(j + 4) - gridc(j + 1)));
                f[(j + 1) * FP] = l * b2[j] + r * b2[j + 1];
            }
        }
        __syncthreads();

        // ---- Phase 3: MAC over this i-chunk ----
        #pragma unroll 1
        for (int iL = 0; iL < I_CHUNK; iL++) {
            const int i = h * I_CHUNK + iL;
            #pragma unroll 3
            for (int c = 0; c < NC; c++) {
                const float* frow = Fs + (iL * NC + c) * FP + wt * 4;
                // group A: [wt*4, wt*4+8)      — lane stride 16B, conflict-free
                float4 a0 = *(const float4*)(frow);
                float4 a1 = *(const float4*)(frow + 4);
                // group B: [wt*4+128, wt*4+136)
                float4 c0 = *(const float4*)(frow + HALF_W);
                float4 c1 = *(const float4*)(frow + HALF_W + 4);

                unsigned long long fsA[8], fsB[8];
                fsA[0] = splat2(a0.x); fsA[1] = splat2(a0.y);
                fsA[2] = splat2(a0.z); fsA[3] = splat2(a0.w);
                fsA[4] = splat2(a1.x); fsA[5] = splat2(a1.y);
                fsA[6] = splat2(a1.z); fsA[7] = splat2(a1.w);
                fsB[0] = splat2(c0.x); fsB[1] = splat2(c0.y);
                fsB[2] = splat2(c0.z); fsB[3] = splat2(c0.w);
                fsB[4] = splat2(c1.x); fsB[5] = splat2(c1.y);
                fsB[6] = splat2(c1.z); fsB[7] = splat2(c1.w);

                #pragma unroll
                for (int k = 0; k < KSZ; k++) {
                    // two broadcast LDS.128: weight octet {o0..o0+7} = 4 f32x2 pairs
                    const float* wrow = &Wc[((i * KSZ + k) * NC + c) * O_DIM + o0];
                    ulonglong2 wq0 = *(const ulonglong2*)(wrow);
                    ulonglong2 wq1 = *(const ulonglong2*)(wrow + 4);
                    #pragma unroll
                    for (int u = 0; u < 4; u++) {
                        ffma2(acc[0][0][u], wq0.x, fsA[u + k]);
                        ffma2(acc[0][1][u], wq0.y, fsA[u + k]);
                        ffma2(acc[0][2][u], wq1.x, fsA[u + k]);
                        ffma2(acc[0][3][u], wq1.y, fsA[u + k]);
                        ffma2(acc[1][0][u], wq0.x, fsB[u + k]);
                        ffma2(acc[1][1][u], wq0.y, fsB[u + k]);
                        ffma2(acc[1][2][u], wq1.x, fsB[u + k]);
                        ffma2(acc[1][3][u], wq1.y, fsB[u + k]);
                    }
                }
            }
        }
    }

    // ---- Phase 4: store. 8 o-rows x (2 groups x 4 w) per thread. ----
    #pragma unroll
    for (int g = 0; g < 2; g++) {
        const int wbase = w0 + wt * 4 + g * HALF_W;
        const bool full = (wbase + 4 <= W_OUT);
        #pragma unroll
        for (int p = 0; p < 4; p++) {
            float lv[4], hv[4];
            #pragma unroll
            for (int u = 0; u < 4; u++) {
                lv[u] = lo32(acc[g][p][u]);
                hv[u] = hi32(acc[g][p][u]);
            }
            int olo = o0 + 2 * p;
            float* rlo = out + ((size_t)(b * O_DIM + olo)) * W_OUT + wbase;
            float* rhi = rlo + W_OUT;
            if (full) {
                *(float4*)rlo = make_float4(lv[0], lv[1], lv[2], lv[3]);
                *(float4*)rhi = make_float4(hv[0], hv[1], hv[2], hv[3]);
            } else {
                #pragma unroll
                for (int u = 0; u < 4; u++) {
                    if (wbase + u < W_OUT) {
                        rlo[u] = lv[u];
                        rhi[u] = hv[u];
                    }
                }
            }
        }
    }
}

extern "C" void kernel_launch(void* const* d_in, const int* in_sizes, int n_in,
                              void* d_out, int out_size)
{
    const float* x             = (const float*)d_in[0];
    const float* base_weight   = (const float*)d_in[1];
    const float* spline_weight = (const float*)d_in[2];
    const float* spline_scaler = (const float*)d_in[3];
    float* out = (float*)d_out;

    size_t smem_bytes = SMEM_FLOATS * sizeof(float);   // 64800
    cudaFuncSetAttribute(kan_conv1d_kernel,
                         cudaFuncAttributeMaxDynamicSharedMemorySize,
                         (int)smem_bytes);

    dim3 grid(NTILES, B_DIM);   // 32 x 32
    kan_conv1d_kernel<<<grid, NTHREADS, smem_bytes>>>(
        x, base_weight, spline_weight, spline_scaler, out);
}